// round 9
// baseline (speedup 1.0000x reference)
#include <cuda_runtime.h>

// ---------------------------------------------------------------------------
// QuanvolutionQLSTM on GB300 (sm_103a)
// 3 launches: conv -> scratch, weight transpose -> scratch, persistent LSTM.
// Persistent LSTM: grid 128, block 256, 1 CTA/SM, 32 batch rows per CTA.
// GEMM core: packed fp32 FFMA2 (fma.rn.f32x2). Weights streamed L2->SMEM via
// cp.async into a 3-buffer ring (4 slices x 33 k-rows cover K=132 exactly),
// ONE barrier per slice (reuse distance 3 makes the post-gemm barrier
// redundant). Activations via single-MUFU tanh.approx. x_t prefetched one
// step ahead in registers.
// ---------------------------------------------------------------------------

#define NSTEP   196
#define CSTRIDE 40              // comb row stride in floats (160B)
#define WSTRIDE 516             // weight slice row stride in floats (2064B, 16B-aligned)
#define S_ROWS  33              // k-rows per slice
#define NSLICE  4               // 4*33 = 132 = K exactly
#define NBUF    3               // weight ring buffers
#define SEQ_F   (NSTEP*128)     // per-block x slab floats
#define COMB_F  (132*CSTRIDE)   // 5280 floats (rows 0..127 h, 128..131 x)
#define WBUF_F  (NBUF*S_ROWS*WSTRIDE) // 51084 floats
#define SMEM_F  (COMB_F + WBUF_F)
#define SMEM_BYTES (SMEM_F*4)   // 225,456 B (< 232,448 opt-in)
#define CHUNKS  (S_ROWS*128)    // 4224 16B-chunks per slice

// Scratch (static device globals: allocation-free per harness rules)
__device__ float g_seq[128 * SEQ_F];   // [block][t][mm][c]  ~12.8MB (L2-resident)
__device__ float g_WT[132 * 512];      // [k][n'], n' = 4*h + gate
__device__ float g_bperm[512];         // bias in same n' permutation

// ---------------------------- small helpers --------------------------------

__device__ __forceinline__ unsigned long long pack2(float lo, float hi) {
    unsigned long long r;
    asm("mov.b64 %0, {%1,%2};" : "=l"(r) : "f"(lo), "f"(hi));
    return r;
}
__device__ __forceinline__ unsigned long long dup2(float x) { return pack2(x, x); }

__device__ __forceinline__ void unpack2(unsigned long long v, float& lo, float& hi) {
    asm("mov.b64 {%0,%1}, %2;" : "=f"(lo), "=f"(hi) : "l"(v));
}

// d += a * b on packed f32x2 (SASS FFMA2; sm_100+ only)
__device__ __forceinline__ void fma2(unsigned long long& d,
                                     unsigned long long a,
                                     unsigned long long b) {
    asm("fma.rn.f32x2 %0, %1, %2, %0;" : "+l"(d) : "l"(a), "l"(b));
}

__device__ __forceinline__ void cp16(void* dst_smem, const void* src_gmem) {
    unsigned d = (unsigned)__cvta_generic_to_shared(dst_smem);
    asm volatile("cp.async.cg.shared.global [%0], [%1], 16;"
                 :: "r"(d), "l"(src_gmem));
}
__device__ __forceinline__ void cp_commit() {
    asm volatile("cp.async.commit_group;");
}
template <int N>
__device__ __forceinline__ void cp_wait() {
    asm volatile("cp.async.wait_group %0;" :: "n"(N));
}

// single-MUFU activations (MUFU.TANH): abs err ~1e-5, gate is 1e-3
__device__ __forceinline__ float tanh_ap(float x) {
    float y;
    asm("tanh.approx.f32 %0, %1;" : "=f"(y) : "f"(x));
    return y;
}
__device__ __forceinline__ float sig_ap(float x) {
    return fmaf(0.5f, tanh_ap(0.5f * x), 0.5f);
}

// ------------------------------- conv --------------------------------------
// 2x2 stride-2 conv, 1->4 channels. grid=4096 (batch), block=196 (patches).
__global__ void conv_kernel(const float* __restrict__ x,
                            const float* __restrict__ cw,
                            const float* __restrict__ cb) {
    int m = blockIdx.x;
    int t = threadIdx.x;           // patch id = i*14 + j
    int i = t / 14, j = t % 14;
    const float* xp = x + m * 784 + (2 * i) * 28 + 2 * j;
    float x00 = xp[0], x01 = xp[1], x10 = xp[28], x11 = xp[29];
    float rv[4];
#pragma unroll
    for (int c = 0; c < 4; c++) {
        rv[c] = cb[c] + x00 * cw[c * 4 + 0] + x01 * cw[c * 4 + 1]
                      + x10 * cw[c * 4 + 2] + x11 * cw[c * 4 + 3];
    }
    float4 r = make_float4(rv[0], rv[1], rv[2], rv[3]);
    // slab layout: [block][t][mm][c], 16B aligned
    *(float4*)(g_seq + (size_t)(((m >> 5) * NSTEP + t) * 32 + (m & 31)) * 4) = r;
}

// --------------------------- weight transpose -------------------------------
// g_WT[k][n'] with n' = 4*h + g (g: 0=f,1=i,2=g,3=o).
// k 0..127   -> W[g][h][4+k]  (h-recurrent; comb rows 0..127 hold h)
// k 128..131 -> W[g][h][k-128] (x part; comb rows 128..131 hold x_t)
__global__ void wt_kernel(const float* __restrict__ Wf, const float* __restrict__ bf_,
                          const float* __restrict__ Wi, const float* __restrict__ bi_,
                          const float* __restrict__ Wg, const float* __restrict__ bg_,
                          const float* __restrict__ Wo, const float* __restrict__ bo_) {
    int n = threadIdx.x;           // 0..511
    int h = n >> 2, g = n & 3;
    const float* W = (g == 0) ? Wf : (g == 1) ? Wi : (g == 2) ? Wg : Wo;
    const float* B = (g == 0) ? bf_ : (g == 1) ? bi_ : (g == 2) ? bg_ : bo_;
    for (int k = 0; k < 128; k++)  g_WT[k * 512 + n] = W[h * 132 + 4 + k];
    for (int k = 0; k < 4; k++)    g_WT[(128 + k) * 512 + n] = W[h * 132 + k];
    g_bperm[n] = B[h];
}

// ------------------------------ LSTM core -----------------------------------

__device__ __forceinline__ void stage_slice(float* wbuf, int sl, int buf, int tid) {
    float* dst = wbuf + buf * (S_ROWS * WSTRIDE);
    const float* src = g_WT + sl * (S_ROWS * 512);
#pragma unroll
    for (int i = 0; i < 17; i++) {            // ceil(4224/256) = 17 (last half-masked)
        int c = tid + i * 256;
        if (c < CHUNKS) {
            int k = c >> 7;                    // 0..32
            int col = (c & 127) * 4;           // 0..508
            cp16(dst + k * WSTRIDE + col, src + k * 512 + col);
        }
    }
}

__device__ __forceinline__ void gemm_slice(unsigned long long (&acc)[4][8],
                                           const float* cb, const float* wb) {
#pragma unroll 3
    for (int kk = 0; kk < S_ROWS; kk++) {
        // A: 8 batch values (4 f32x2 pairs), shared across ni within warp
        ulonglong2 av01 = *(const ulonglong2*)(cb + kk * CSTRIDE);
        ulonglong2 av23 = *(const ulonglong2*)(cb + kk * CSTRIDE + 4);
        unsigned long long av[4] = {av01.x, av01.y, av23.x, av23.y};
        // W: 8 gate-output weights, duplicated into both lanes
        float4 w0 = *(const float4*)(wb + kk * WSTRIDE);
        float4 w1 = *(const float4*)(wb + kk * WSTRIDE + 4);
        unsigned long long wd[8] = {dup2(w0.x), dup2(w0.y), dup2(w0.z), dup2(w0.w),
                                    dup2(w1.x), dup2(w1.y), dup2(w1.z), dup2(w1.w)};
#pragma unroll
        for (int p = 0; p < 4; p++)
#pragma unroll
            for (int j = 0; j < 8; j++)
                fma2(acc[p][j], av[p], wd[j]);
    }
}

__global__ void __launch_bounds__(256, 1)
lstm_kernel(const float* __restrict__ clf_w,
            const float* __restrict__ clf_b,
            float* __restrict__ out) {
    extern __shared__ float sm[];
    float* comb = sm;                  // [k][m] k<132 (rows 0..127=h, 128..131=x)
    float* wbuf = sm + COMB_F;         // [NBUF][S_ROWS][WSTRIDE]

    const int tid = threadIdx.x;
    const int b = blockIdx.x;
    const int mi = tid & 3;            // m-group: m in [8*mi, 8*mi+8)
    const int ni = tid >> 2;           // n-group: n' in [8*ni, 8*ni+8) -> h in {2ni,2ni+1}

    // zero comb (h0 = 0)
    for (int i = tid; i < COMB_F; i += 256) comb[i] = 0.0f;

    unsigned long long bd[8];
#pragma unroll
    for (int j = 0; j < 8; j++) bd[j] = dup2(g_bperm[ni * 8 + j]);

    float cst[2][8];                   // c state: [hh][2*p + lane]
#pragma unroll
    for (int hh = 0; hh < 2; hh++)
#pragma unroll
        for (int q = 0; q < 8; q++) cst[hh][q] = 0.0f;

    // prefetch x_0 and stage weight slice 0 (ring buffer 0)
    float xreg = 0.0f;
    if (tid < 128) xreg = g_seq[(size_t)b * SEQ_F + tid];
    stage_slice(wbuf, 0, 0, tid);
    cp_commit();

    __syncthreads();

    const float* cbase = comb + mi * 8;
    const float* wbase = wbuf + ni * 8;
    float* hrow0 = comb + (2 * ni) * CSTRIDE + mi * 8;
    float* hrow1 = comb + (2 * ni + 1) * CSTRIDE + mi * 8;

    int scnt = 0;      // global slice counter
    int buf = 0;       // ring position = scnt % NBUF (tracked incrementally)

    // ------------------------- time loop -------------------------
    for (int t = 0; t < NSTEP; t++) {
        // x_t into comb rows 128..131 (prefetched last step)
        if (tid < 128) {
            comb[(128 + (tid & 3)) * CSTRIDE + (tid >> 2)] = xreg;
        }
        __syncthreads();   // h (prev epilogue) + x visible to all

        // prefetch x_{t+1}; consumed at next top (latency hidden by gemm)
        if (tid < 128 && t + 1 < NSTEP) {
            xreg = g_seq[(size_t)b * SEQ_F + (t + 1) * 128 + tid];
        }

        unsigned long long acc[4][8];
#pragma unroll
        for (int p = 0; p < 4; p++)
#pragma unroll
            for (int j = 0; j < 8; j++) acc[p][j] = bd[j];

        for (int s = 0; s < NSLICE; s++) {
            bool last_all = (t == NSTEP - 1) && (s == NSLICE - 1);
            int nbuf = (buf + 1 < NBUF) ? buf + 1 : 0;
            if (!last_all) {
                // stage next slice (wraps to slice 0 of next step).
                // Ring reuse distance 3 => all readers of 'nbuf' passed the
                // barrier two slices ago; safe without a post-gemm barrier.
                int nsl = (s + 1 < NSLICE) ? s + 1 : 0;
                stage_slice(wbuf, nsl, nbuf, tid);
                cp_commit();
                cp_wait<1>();          // current slice's group done
            } else {
                cp_wait<0>();
            }
            __syncthreads();           // staged slice s visible to all
            gemm_slice(acc, cbase + s * (S_ROWS * CSTRIDE),
                       wbase + buf * (S_ROWS * WSTRIDE));
            scnt++;
            buf = nbuf;
        }

        // ---- epilogue: gates -> c,h; h back into comb rows [0,128) ----
#pragma unroll
        for (int hh = 0; hh < 2; hh++) {
#pragma unroll
            for (int p = 0; p < 4; p++) {
                float f0, f1, i0, i1, g0, g1, o0, o1;
                unpack2(acc[p][hh * 4 + 0], f0, f1);
                unpack2(acc[p][hh * 4 + 1], i0, i1);
                unpack2(acc[p][hh * 4 + 2], g0, g1);
                unpack2(acc[p][hh * 4 + 3], o0, o1);
                float c0 = cst[hh][2 * p + 0], c1 = cst[hh][2 * p + 1];
                c0 = sig_ap(f0) * c0 + sig_ap(i0) * tanh_ap(g0);
                c1 = sig_ap(f1) * c1 + sig_ap(i1) * tanh_ap(g1);
                cst[hh][2 * p + 0] = c0;
                cst[hh][2 * p + 1] = c1;
                float h0 = sig_ap(o0) * tanh_ap(c0);
                float h1 = sig_ap(o1) * tanh_ap(c1);
                *(float2*)((hh ? hrow1 : hrow0) + 2 * p) = make_float2(h0, h1);
            }
        }
        // next iteration's top __syncthreads() orders these h stores
    }

    __syncthreads();

    // ---- classifier + log_softmax: one thread per batch row (once) ----
    if (tid < 32) {
        int m = tid;
        float logit[10];
#pragma unroll
        for (int c = 0; c < 10; c++) {
            float s = clf_b[c];
            for (int h = 0; h < 128; h++)
                s += comb[h * CSTRIDE + m] * clf_w[c * 128 + h];
            logit[c] = s;
        }
        float mx = logit[0];
#pragma unroll
        for (int c = 1; c < 10; c++) mx = fmaxf(mx, logit[c]);
        float sum = 0.0f;
#pragma unroll
        for (int c = 0; c < 10; c++) sum += expf(logit[c] - mx);
        float lse = mx + logf(sum);
        float* orow = out + (size_t)(b * 32 + m) * 10;
#pragma unroll
        for (int c = 0; c < 10; c++) orow[c] = logit[c] - lse;
    }
}

// ------------------------------- launch -------------------------------------

extern "C" void kernel_launch(void* const* d_in, const int* in_sizes, int n_in,
                              void* d_out, int out_size) {
    const float* x      = (const float*)d_in[0];
    const float* conv_w = (const float*)d_in[1];
    const float* conv_b = (const float*)d_in[2];
    const float* Wf = (const float*)d_in[3];  const float* bf_ = (const float*)d_in[4];
    const float* Wi = (const float*)d_in[5];  const float* bi_ = (const float*)d_in[6];
    const float* Wg = (const float*)d_in[7];  const float* bg_ = (const float*)d_in[8];
    const float* Wo = (const float*)d_in[9];  const float* bo_ = (const float*)d_in[10];
    const float* clf_w = (const float*)d_in[11];
    const float* clf_b = (const float*)d_in[12];
    float* out = (float*)d_out;

    conv_kernel<<<4096, NSTEP>>>(x, conv_w, conv_b);
    wt_kernel<<<1, 512>>>(Wf, bf_, Wi, bi_, Wg, bg_, Wo, bo_);

    cudaFuncSetAttribute(lstm_kernel,
                         cudaFuncAttributeMaxDynamicSharedMemorySize, SMEM_BYTES);
    lstm_kernel<<<128, 256, SMEM_BYTES>>>(clf_w, clf_b, out);

    (void)in_sizes; (void)n_in; (void)out_size;
}

// round 13
// speedup vs baseline: 1.0772x; 1.0772x over previous
#include <cuda_runtime.h>

// ---------------------------------------------------------------------------
// QuanvolutionQLSTM on GB300 (sm_103a)
// R3-measured-good structure (2552.8us): 3 slices x 44 k-rows, double-buffered
// cp.async weight streaming, 7 barriers/step. Single change vs R3: epilogue
// activations use single-MUFU tanh.approx (proven harmless at rel_err 7e-8
// in R9's measurement of the ring variant).
// ---------------------------------------------------------------------------

#define NSTEP   196
#define CSTRIDE 40              // comb row stride in floats (160B)
#define WSTRIDE 520             // weight slice row stride in floats (2080B)
#define S_ROWS  44              // k-rows per slice
#define NSLICE  3               // 3*44 = 132 = K exactly
#define SEQ_F   (NSTEP*128)     // per-block x slab floats
#define COMB_F  (132*CSTRIDE)   // 5280 floats (rows 0..127 h, 128..131 x)
#define WBUF_F  (2*S_ROWS*WSTRIDE) // 45760 floats
#define SMEM_F  (COMB_F + WBUF_F)
#define SMEM_BYTES (SMEM_F*4)   // 204,160 B (< 227KB opt-in)

// Scratch (static device globals: allocation-free per harness rules)
__device__ float g_seq[128 * SEQ_F];   // [block][t][mm][c]  ~12.8MB (L2-resident)
__device__ float g_WT[132 * 512];      // [k][n'], n' = 4*h + gate
__device__ float g_bperm[512];         // bias in same n' permutation

// ---------------------------- small helpers --------------------------------

__device__ __forceinline__ unsigned long long pack2(float lo, float hi) {
    unsigned long long r;
    asm("mov.b64 %0, {%1,%2};" : "=l"(r) : "f"(lo), "f"(hi));
    return r;
}
__device__ __forceinline__ unsigned long long dup2(float x) { return pack2(x, x); }

__device__ __forceinline__ void unpack2(unsigned long long v, float& lo, float& hi) {
    asm("mov.b64 {%0,%1}, %2;" : "=f"(lo), "=f"(hi) : "l"(v));
}

// d += a * b on packed f32x2 (SASS FFMA2; sm_100+ only)
__device__ __forceinline__ void fma2(unsigned long long& d,
                                     unsigned long long a,
                                     unsigned long long b) {
    asm("fma.rn.f32x2 %0, %1, %2, %0;" : "+l"(d) : "l"(a), "l"(b));
}

__device__ __forceinline__ void cp16(void* dst_smem, const void* src_gmem) {
    unsigned d = (unsigned)__cvta_generic_to_shared(dst_smem);
    asm volatile("cp.async.cg.shared.global [%0], [%1], 16;"
                 :: "r"(d), "l"(src_gmem));
}
__device__ __forceinline__ void cp_commit() {
    asm volatile("cp.async.commit_group;");
}
template <int N>
__device__ __forceinline__ void cp_wait() {
    asm volatile("cp.async.wait_group %0;" :: "n"(N));
}

// single-MUFU activations (MUFU.TANH): measured harmless (rel_err ~7e-8)
__device__ __forceinline__ float tanh_ap(float x) {
    float y;
    asm("tanh.approx.f32 %0, %1;" : "=f"(y) : "f"(x));
    return y;
}
__device__ __forceinline__ float sig_ap(float x) {
    return fmaf(0.5f, tanh_ap(0.5f * x), 0.5f);
}

// ------------------------------- conv --------------------------------------
// 2x2 stride-2 conv, 1->4 channels. grid=4096 (batch), block=196 (patches).
__global__ void conv_kernel(const float* __restrict__ x,
                            const float* __restrict__ cw,
                            const float* __restrict__ cb) {
    int m = blockIdx.x;
    int t = threadIdx.x;           // patch id = i*14 + j
    int i = t / 14, j = t % 14;
    const float* xp = x + m * 784 + (2 * i) * 28 + 2 * j;
    float x00 = xp[0], x01 = xp[1], x10 = xp[28], x11 = xp[29];
    float rv[4];
#pragma unroll
    for (int c = 0; c < 4; c++) {
        rv[c] = cb[c] + x00 * cw[c * 4 + 0] + x01 * cw[c * 4 + 1]
                      + x10 * cw[c * 4 + 2] + x11 * cw[c * 4 + 3];
    }
    float4 r = make_float4(rv[0], rv[1], rv[2], rv[3]);
    // slab layout: [block][t][mm][c], 16B aligned
    *(float4*)(g_seq + (size_t)(((m >> 5) * NSTEP + t) * 32 + (m & 31)) * 4) = r;
}

// --------------------------- weight transpose -------------------------------
// g_WT[k][n'] with n' = 4*h + g (g: 0=f,1=i,2=g,3=o).
// k 0..127   -> W[g][h][4+k]  (h-recurrent; comb rows 0..127 hold h)
// k 128..131 -> W[g][h][k-128] (x part; comb rows 128..131 hold x_t)
__global__ void wt_kernel(const float* __restrict__ Wf, const float* __restrict__ bf_,
                          const float* __restrict__ Wi, const float* __restrict__ bi_,
                          const float* __restrict__ Wg, const float* __restrict__ bg_,
                          const float* __restrict__ Wo, const float* __restrict__ bo_) {
    int n = threadIdx.x;           // 0..511
    int h = n >> 2, g = n & 3;
    const float* W = (g == 0) ? Wf : (g == 1) ? Wi : (g == 2) ? Wg : Wo;
    const float* B = (g == 0) ? bf_ : (g == 1) ? bi_ : (g == 2) ? bg_ : bo_;
    for (int k = 0; k < 128; k++)  g_WT[k * 512 + n] = W[h * 132 + 4 + k];
    for (int k = 0; k < 4; k++)    g_WT[(128 + k) * 512 + n] = W[h * 132 + k];
    g_bperm[n] = B[h];
}

// ------------------------------ LSTM core -----------------------------------

__device__ __forceinline__ void stage_slice(float* wbuf, int sl, int buf, int tid) {
    float* dst = wbuf + buf * (S_ROWS * WSTRIDE);
    const float* src = g_WT + sl * (S_ROWS * 512);
#pragma unroll
    for (int i = 0; i < 22; i++) {            // 22*256 = 5632 = 44*128 chunks
        int c = tid + i * 256;
        int k = c >> 7;                        // 0..43
        int col = (c & 127) * 4;               // 0..508
        cp16(dst + k * WSTRIDE + col, src + k * 512 + col);
    }
}

__device__ __forceinline__ void gemm_slice(unsigned long long (&acc)[4][8],
                                           const float* cb, const float* wb) {
#pragma unroll 4
    for (int kk = 0; kk < S_ROWS; kk++) {
        // A: 8 batch values (4 f32x2 pairs), shared across ni within warp
        ulonglong2 av01 = *(const ulonglong2*)(cb + kk * CSTRIDE);
        ulonglong2 av23 = *(const ulonglong2*)(cb + kk * CSTRIDE + 4);
        unsigned long long av[4] = {av01.x, av01.y, av23.x, av23.y};
        // W: 8 gate-output weights, duplicated into both lanes
        float4 w0 = *(const float4*)(wb + kk * WSTRIDE);
        float4 w1 = *(const float4*)(wb + kk * WSTRIDE + 4);
        unsigned long long wd[8] = {dup2(w0.x), dup2(w0.y), dup2(w0.z), dup2(w0.w),
                                    dup2(w1.x), dup2(w1.y), dup2(w1.z), dup2(w1.w)};
#pragma unroll
        for (int p = 0; p < 4; p++)
#pragma unroll
            for (int j = 0; j < 8; j++)
                fma2(acc[p][j], av[p], wd[j]);
    }
}

__global__ void __launch_bounds__(256, 1)
lstm_kernel(const float* __restrict__ clf_w,
            const float* __restrict__ clf_b,
            float* __restrict__ out) {
    extern __shared__ float sm[];
    float* comb = sm;                  // [k][m] k<132 (rows 0..127=h, 128..131=x)
    float* wbuf = sm + COMB_F;         // [2][S_ROWS][WSTRIDE]

    const int tid = threadIdx.x;
    const int b = blockIdx.x;
    const int mi = tid & 3;            // m-group: m in [8*mi, 8*mi+8)
    const int ni = tid >> 2;           // n-group: n' in [8*ni, 8*ni+8) -> h in {2ni,2ni+1}

    // zero comb (h0 = 0)
    for (int i = tid; i < COMB_F; i += 256) comb[i] = 0.0f;

    unsigned long long bd[8];
#pragma unroll
    for (int j = 0; j < 8; j++) bd[j] = dup2(g_bperm[ni * 8 + j]);

    float cst[2][8];                   // c state: [hh][2*p + lane]
#pragma unroll
    for (int hh = 0; hh < 2; hh++)
#pragma unroll
        for (int q = 0; q < 8; q++) cst[hh][q] = 0.0f;

    // prefetch x_0 and stage weight slice 0 (buffer 0)
    float xreg = 0.0f;
    if (tid < 128) xreg = g_seq[(size_t)b * SEQ_F + tid];
    stage_slice(wbuf, 0, 0, tid);
    cp_commit();

    __syncthreads();

    const float* cbase = comb + mi * 8;
    const float* wbase = wbuf + ni * 8;
    float* hrow0 = comb + (2 * ni) * CSTRIDE + mi * 8;
    float* hrow1 = comb + (2 * ni + 1) * CSTRIDE + mi * 8;

    int scnt = 0;   // global slice counter; buffer = scnt & 1

    // ------------------------- time loop -------------------------
    for (int t = 0; t < NSTEP; t++) {
        // x_t into comb rows 128..131 (prefetched last step)
        if (tid < 128) {
            comb[(128 + (tid & 3)) * CSTRIDE + (tid >> 2)] = xreg;
        }
        __syncthreads();   // h (prev epilogue) + x visible to all

        // prefetch x_{t+1}; consumed at next top (latency hidden by gemm)
        if (tid < 128 && t + 1 < NSTEP) {
            xreg = g_seq[(size_t)b * SEQ_F + (t + 1) * 128 + tid];
        }

        unsigned long long acc[4][8];
#pragma unroll
        for (int p = 0; p < 4; p++)
#pragma unroll
            for (int j = 0; j < 8; j++) acc[p][j] = bd[j];

        for (int s = 0; s < NSLICE; s++) {
            bool last_all = (t == NSTEP - 1) && (s == NSLICE - 1);
            if (!last_all) {
                // stage next slice (wraps to slice 0 of next step)
                int nsl = (s + 1 < NSLICE) ? s + 1 : 0;
                stage_slice(wbuf, nsl, (scnt + 1) & 1, tid);
                cp_commit();
                cp_wait<1>();          // current slice's group done
            } else {
                cp_wait<0>();
            }
            __syncthreads();           // staged slice visible to all
            gemm_slice(acc, cbase + s * (S_ROWS * CSTRIDE),
                       wbase + (scnt & 1) * (S_ROWS * WSTRIDE));
            __syncthreads();           // all reads done before buffer reuse
            scnt++;
        }

        // ---- epilogue: gates -> c,h; h back into comb rows [0,128) ----
#pragma unroll
        for (int hh = 0; hh < 2; hh++) {
#pragma unroll
            for (int p = 0; p < 4; p++) {
                float f0, f1, i0, i1, g0, g1, o0, o1;
                unpack2(acc[p][hh * 4 + 0], f0, f1);
                unpack2(acc[p][hh * 4 + 1], i0, i1);
                unpack2(acc[p][hh * 4 + 2], g0, g1);
                unpack2(acc[p][hh * 4 + 3], o0, o1);
                float c0 = cst[hh][2 * p + 0], c1 = cst[hh][2 * p + 1];
                c0 = sig_ap(f0) * c0 + sig_ap(i0) * tanh_ap(g0);
                c1 = sig_ap(f1) * c1 + sig_ap(i1) * tanh_ap(g1);
                cst[hh][2 * p + 0] = c0;
                cst[hh][2 * p + 1] = c1;
                float h0 = sig_ap(o0) * tanh_ap(c0);
                float h1 = sig_ap(o1) * tanh_ap(c1);
                *(float2*)((hh ? hrow1 : hrow0) + 2 * p) = make_float2(h0, h1);
            }
        }
        // next iteration's top __syncthreads() orders these h stores
    }

    __syncthreads();

    // ---- classifier + log_softmax: one thread per batch row (once) ----
    if (tid < 32) {
        int m = tid;
        float logit[10];
#pragma unroll
        for (int c = 0; c < 10; c++) {
            float s = clf_b[c];
            for (int h = 0; h < 128; h++)
                s += comb[h * CSTRIDE + m] * clf_w[c * 128 + h];
            logit[c] = s;
        }
        float mx = logit[0];
#pragma unroll
        for (int c = 1; c < 10; c++) mx = fmaxf(mx, logit[c]);
        float sum = 0.0f;
#pragma unroll
        for (int c = 0; c < 10; c++) sum += expf(logit[c] - mx);
        float lse = mx + logf(sum);
        float* orow = out + (size_t)(b * 32 + m) * 10;
#pragma unroll
        for (int c = 0; c < 10; c++) orow[c] = logit[c] - lse;
    }
}

// ------------------------------- launch -------------------------------------

extern "C" void kernel_launch(void* const* d_in, const int* in_sizes, int n_in,
                              void* d_out, int out_size) {
    const float* x      = (const float*)d_in[0];
    const float* conv_w = (const float*)d_in[1];
    const float* conv_b = (const float*)d_in[2];
    const float* Wf = (const float*)d_in[3];  const float* bf_ = (const float*)d_in[4];
    const float* Wi = (const float*)d_in[5];  const float* bi_ = (const float*)d_in[6];
    const float* Wg = (const float*)d_in[7];  const float* bg_ = (const float*)d_in[8];
    const float* Wo = (const float*)d_in[9];  const float* bo_ = (const float*)d_in[10];
    const float* clf_w = (const float*)d_in[11];
    const float* clf_b = (const float*)d_in[12];
    float* out = (float*)d_out;

    conv_kernel<<<4096, NSTEP>>>(x, conv_w, conv_b);
    wt_kernel<<<1, 512>>>(Wf, bf_, Wi, bi_, Wg, bg_, Wo, bo_);

    cudaFuncSetAttribute(lstm_kernel,
                         cudaFuncAttributeMaxDynamicSharedMemorySize, SMEM_BYTES);
    lstm_kernel<<<128, 256, SMEM_BYTES>>>(clf_w, clf_b, out);

    (void)in_sizes; (void)n_in; (void)out_size;
}